// round 4
// baseline (speedup 1.0000x reference)
#include <cuda_runtime.h>
#include <cuda_bf16.h>

#define BLK 256

// Persistent scratch: 4 accumulators + arrival counter.
// Invariant: zero before each kernel_launch call (zeroed statically at load,
// re-zeroed by the finalizing block each run) -> graph-replay deterministic.
__device__ float g_acc[4] = {0.f, 0.f, 0.f, 0.f};
__device__ unsigned int g_ticket = 0u;

template <int N4>
__global__ __launch_bounds__(BLK) void ccel_kernel(
    const float* __restrict__ input,
    const int* __restrict__ target,
    const float* __restrict__ X1,
    const int* __restrict__ Y1,
    const float* __restrict__ X2,
    const int* __restrict__ Y2,
    const float* __restrict__ T,
    float* __restrict__ out,
    float invB, unsigned int nblocks)
{
    const int row = blockIdx.x;
    const int tid = threadIdx.x;
    const size_t base = (size_t)row * (size_t)(N4 * 4);
    const float4* __restrict__ rp = reinterpret_cast<const float4*>(input + base);

    // Thread 0 issues the dependent gather chain early so its latency
    // overlaps the block's streaming-sum loop.
    float xt = 0.f, xy1 = 0.f, xy2 = 0.f, x1v = 0.f, x2v = 0.f, t0 = 0.f;
    if (tid == 0) {
        int tgt = target[row];
        int y1  = Y1[tgt];
        int y2  = Y2[tgt];
        x1v = X1[tgt];
        x2v = X2[tgt];
        t0  = T[0];
        xt  = input[base + (size_t)tgt];
        xy1 = input[base + (size_t)y1];
        xy2 = input[base + (size_t)y2];
    }

    // One streaming pass: sum of exp(x). 4 front-batched independent loads
    // per iteration (MLP_p1=4) + 4 accumulators; compile-time trip count.
    float s0 = 0.f, s1 = 0.f, s2 = 0.f, s3 = 0.f;
    int i = tid;
    for (; i + 3 * BLK < N4; i += 4 * BLK) {
        float4 a = __ldcs(rp + i);
        float4 b = __ldcs(rp + i + BLK);
        float4 c = __ldcs(rp + i + 2 * BLK);
        float4 d = __ldcs(rp + i + 3 * BLK);
        s0 += __expf(a.x) + __expf(a.y) + __expf(a.z) + __expf(a.w);
        s1 += __expf(b.x) + __expf(b.y) + __expf(b.z) + __expf(b.w);
        s2 += __expf(c.x) + __expf(c.y) + __expf(c.z) + __expf(c.w);
        s3 += __expf(d.x) + __expf(d.y) + __expf(d.z) + __expf(d.w);
    }
    for (; i < N4; i += BLK) {
        float4 a = __ldcs(rp + i);
        s0 += __expf(a.x) + __expf(a.y) + __expf(a.z) + __expf(a.w);
    }
    float s = (s0 + s1) + (s2 + s3);

    // Warp reduce
    #pragma unroll
    for (int o = 16; o; o >>= 1) s += __shfl_xor_sync(0xffffffffu, s, o);

    __shared__ float ws[BLK / 32];
    if ((tid & 31) == 0) ws[tid >> 5] = s;
    __syncthreads();

    if (tid == 0) {
        float S = 0.0f;
        #pragma unroll
        for (int w = 0; w < BLK / 32; w++) S += ws[w];

        float Et = __expf(xt);
        float E1 = __expf(xy1);
        float E2 = __expf(xy2);
        float num = t0 * (x1v * E1 + x2v * E2);   // corr * S
        bool  cond = Et > num;                    // p_t > corr  (shared S > 0)
        float logS = __logf(S);

        // cond:  -log(p_t - corr) = logS - log(Et - num)
        // else:  -log(p_t)        = logS - xt
        float loss = cond ? (logS - __logf(Et - num)) : (logS - xt);

        float P1 = E1 / S;
        float P2 = E2 / S;
        bool  nz = (P1 != 0.0f) || (P2 != 0.0f);
        bool  k  = cond && nz;
        float z  = k ? (Et / num) : 0.0f;         // p_t / corr

        atomicAdd(&g_acc[0], loss * invB);
        atomicAdd(&g_acc[1], k ? 1.0f : 0.0f);
        atomicAdd(&g_acc[2], z);
        atomicAdd(&g_acc[3], cond ? 0.0f : 1.0f);

        __threadfence();
        unsigned int old = atomicInc(&g_ticket, nblocks - 1u);
        if (old == nblocks - 1u) {
            // Last block: drain scratch into out, leaving scratch zeroed
            // for the next (graph-replayed) run.
            out[0] = atomicExch(&g_acc[0], 0.0f);
            out[1] = atomicExch(&g_acc[1], 0.0f);
            out[2] = atomicExch(&g_acc[2], 0.0f);
            out[3] = atomicExch(&g_acc[3], 0.0f);
        }
    }
}

// Generic-C fallback (runtime trip count)
__global__ __launch_bounds__(BLK) void ccel_kernel_gen(
    const float* __restrict__ input,
    const int* __restrict__ target,
    const float* __restrict__ X1,
    const int* __restrict__ Y1,
    const float* __restrict__ X2,
    const int* __restrict__ Y2,
    const float* __restrict__ T,
    float* __restrict__ out,
    int C, float invB, unsigned int nblocks)
{
    const int row = blockIdx.x;
    const int tid = threadIdx.x;
    const size_t base = (size_t)row * (size_t)C;
    const int n4 = C >> 2;
    const float4* __restrict__ rp = reinterpret_cast<const float4*>(input + base);

    float xt = 0.f, xy1 = 0.f, xy2 = 0.f, x1v = 0.f, x2v = 0.f, t0 = 0.f;
    if (tid == 0) {
        int tgt = target[row];
        int y1  = Y1[tgt];
        int y2  = Y2[tgt];
        x1v = X1[tgt]; x2v = X2[tgt]; t0 = T[0];
        xt  = input[base + (size_t)tgt];
        xy1 = input[base + (size_t)y1];
        xy2 = input[base + (size_t)y2];
    }

    float s = 0.f;
    int i = tid;
    for (; i < n4; i += BLK) {
        float4 a = __ldcs(rp + i);
        s += __expf(a.x) + __expf(a.y) + __expf(a.z) + __expf(a.w);
    }
    for (int c = (n4 << 2) + tid; c < C; c += BLK) s += __expf(input[base + c]);

    #pragma unroll
    for (int o = 16; o; o >>= 1) s += __shfl_xor_sync(0xffffffffu, s, o);
    __shared__ float ws[BLK / 32];
    if ((tid & 31) == 0) ws[tid >> 5] = s;
    __syncthreads();

    if (tid == 0) {
        float S = 0.0f;
        #pragma unroll
        for (int w = 0; w < BLK / 32; w++) S += ws[w];
        float Et = __expf(xt), E1 = __expf(xy1), E2 = __expf(xy2);
        float num = t0 * (x1v * E1 + x2v * E2);
        bool  cond = Et > num;
        float logS = __logf(S);
        float loss = cond ? (logS - __logf(Et - num)) : (logS - xt);
        bool  nz = ((E1 / S) != 0.0f) || ((E2 / S) != 0.0f);
        bool  k  = cond && nz;
        float z  = k ? (Et / num) : 0.0f;
        atomicAdd(&g_acc[0], loss * invB);
        atomicAdd(&g_acc[1], k ? 1.0f : 0.0f);
        atomicAdd(&g_acc[2], z);
        atomicAdd(&g_acc[3], cond ? 0.0f : 1.0f);
        __threadfence();
        unsigned int old = atomicInc(&g_ticket, nblocks - 1u);
        if (old == nblocks - 1u) {
            out[0] = atomicExch(&g_acc[0], 0.0f);
            out[1] = atomicExch(&g_acc[1], 0.0f);
            out[2] = atomicExch(&g_acc[2], 0.0f);
            out[3] = atomicExch(&g_acc[3], 0.0f);
        }
    }
}

extern "C" void kernel_launch(void* const* d_in, const int* in_sizes, int n_in,
                              void* d_out, int out_size) {
    const float* input  = (const float*)d_in[0];
    const int*   target = (const int*)d_in[1];
    const float* X1     = (const float*)d_in[2];
    const int*   Y1     = (const int*)d_in[3];
    const float* X2     = (const float*)d_in[4];
    const int*   Y2     = (const int*)d_in[5];
    const float* T      = (const float*)d_in[6];
    float* out = (float*)d_out;

    int B = in_sizes[1];          // target has B elements
    int C = in_sizes[2];          // X1 has C elements
    float invB = 1.0f / (float)B;

    if (C == 32000) {
        ccel_kernel<8000><<<B, BLK>>>(input, target, X1, Y1, X2, Y2, T, out,
                                      invB, (unsigned int)B);
    } else {
        ccel_kernel_gen<<<B, BLK>>>(input, target, X1, Y1, X2, Y2, T, out,
                                    C, invB, (unsigned int)B);
    }
}

// round 5
// speedup vs baseline: 1.0246x; 1.0246x over previous
#include <cuda_runtime.h>
#include <cuda_bf16.h>

#define BLK 256

// Persistent scratch: 4 accumulators + arrival counter.
// Invariant: zeroed at load; the finalizing block re-zeroes after draining,
// so every graph replay sees the same initial state.
__device__ float g_acc[4] = {0.f, 0.f, 0.f, 0.f};
__device__ unsigned int g_ticket = 0u;

__global__ void __launch_bounds__(BLK, 8) ccel_kernel(
    const float* __restrict__ input,
    const int* __restrict__ target,
    const float* __restrict__ X1,
    const int* __restrict__ Y1,
    const float* __restrict__ X2,
    const int* __restrict__ Y2,
    const float* __restrict__ T,
    float* __restrict__ out,
    int C, float invB, unsigned int nblocks)
{
    const int row = blockIdx.x;
    const int tid = threadIdx.x;
    const size_t base = (size_t)row * (size_t)C;
    const float4* __restrict__ rp = reinterpret_cast<const float4*>(input + base);
    const int n4 = C >> 2;

    // Thread 0 issues the dependent gather chain early so its latency
    // overlaps the block's streaming-sum loop.
    float xt = 0.f, xy1 = 0.f, xy2 = 0.f, x1v = 0.f, x2v = 0.f, t0 = 0.f;
    if (tid == 0) {
        int tgt = target[row];
        int y1  = Y1[tgt];
        int y2  = Y2[tgt];
        x1v = X1[tgt];
        x2v = X2[tgt];
        t0  = T[0];
        xt  = input[base + (size_t)tgt];
        xy1 = input[base + (size_t)y1];
        xy2 = input[base + (size_t)y2];
    }

    // One streaming pass: sum of exp(x). Simple strided float4 loop — 31 regs,
    // 8 CTAs/SM; occupancy supplies the memory-level parallelism.
    float s = 0.0f;
    for (int i = tid; i < n4; i += BLK) {
        float4 v = __ldcs(rp + i);
        s += __expf(v.x);
        s += __expf(v.y);
        s += __expf(v.z);
        s += __expf(v.w);
    }

    // Warp reduce
    #pragma unroll
    for (int o = 16; o; o >>= 1) s += __shfl_xor_sync(0xffffffffu, s, o);

    __shared__ float ws[BLK / 32];
    if ((tid & 31) == 0) ws[tid >> 5] = s;
    __syncthreads();

    if (tid == 0) {
        float S = 0.0f;
        #pragma unroll
        for (int w = 0; w < BLK / 32; w++) S += ws[w];

        float Et = __expf(xt);
        float E1 = __expf(xy1);
        float E2 = __expf(xy2);
        float num = t0 * (x1v * E1 + x2v * E2);   // corr * S
        bool  cond = Et > num;                    // p_t > corr  (shared S > 0)
        float logS = __logf(S);

        // cond:  -log(p_t - corr) = logS - log(Et - num)
        // else:  -log(p_t)        = logS - xt
        float loss = cond ? (logS - __logf(Et - num)) : (logS - xt);

        float P1 = E1 / S;
        float P2 = E2 / S;
        bool  nz = (P1 != 0.0f) || (P2 != 0.0f);
        bool  k  = cond && nz;
        float z  = k ? (Et / num) : 0.0f;         // p_t / corr

        atomicAdd(&g_acc[0], loss * invB);
        atomicAdd(&g_acc[1], k ? 1.0f : 0.0f);
        atomicAdd(&g_acc[2], z);
        atomicAdd(&g_acc[3], cond ? 0.0f : 1.0f);

        __threadfence();
        unsigned int old = atomicInc(&g_ticket, nblocks - 1u);
        if (old == nblocks - 1u) {
            // Last block: drain scratch into out, leaving scratch zeroed
            // for the next (graph-replayed) run.
            out[0] = atomicExch(&g_acc[0], 0.0f);
            out[1] = atomicExch(&g_acc[1], 0.0f);
            out[2] = atomicExch(&g_acc[2], 0.0f);
            out[3] = atomicExch(&g_acc[3], 0.0f);
        }
    }
}

extern "C" void kernel_launch(void* const* d_in, const int* in_sizes, int n_in,
                              void* d_out, int out_size) {
    const float* input  = (const float*)d_in[0];
    const int*   target = (const int*)d_in[1];
    const float* X1     = (const float*)d_in[2];
    const int*   Y1     = (const int*)d_in[3];
    const float* X2     = (const float*)d_in[4];
    const int*   Y2     = (const int*)d_in[5];
    const float* T      = (const float*)d_in[6];
    float* out = (float*)d_out;

    int B = in_sizes[1];          // target has B elements
    int C = in_sizes[2];          // X1 has C elements
    float invB = 1.0f / (float)B;

    ccel_kernel<<<B, BLK>>>(input, target, X1, Y1, X2, Y2, T, out,
                            C, invB, (unsigned int)B);
}